// round 15
// baseline (speedup 1.0000x reference)
#include <cuda_runtime.h>
#include <cstdint>

#define B_ 16
#define N_ 2048
#define F_ 128
#define C1 32
#define TM 64              // rows per CTA tile
#define KT 64              // k-slab: 256B contiguous per A row
#define PA 68              // As pitch: 68%32=4 -> A frags conflict-free
#define PT 40              // Ts pitch: conflict-free B frags
#define NTILES (N_ / TM)   // 32

#define SMEM_BYTES (2*TM*PA*4 + 2*KT*PT*4 + 4*C1*4)   // 55808 B -> 4 CTAs/SM

// Scratch (static device globals — no allocation allowed)
__device__ uint32_t g_Tt[B_ * N_ * C1];      // T1 = X@W1 as tf32 bits
__device__ uint32_t g_T2t[B_ * N_ * C1];     // T2 = elu(A@T1+b1)@W2 as tf32 bits
__device__ float    g_poolpart[B_ * NTILES * C1];
__device__ int      g_cnt[B_];               // agg2 completion tickets per batch

__device__ __forceinline__ float elu_f(float x) {
    return x > 0.f ? x : (__expf(x) - 1.f);
}

__device__ __forceinline__ uint32_t f2tf(float f) {
    uint32_t r;
    asm("cvt.rna.tf32.f32 %0, %1;" : "=r"(r) : "f"(f));
    return r;
}

__device__ __forceinline__ void cp16(void* dst, const void* src) {
    uint32_t d = (uint32_t)__cvta_generic_to_shared(dst);
    asm volatile("cp.async.cg.shared.global [%0], [%1], 16;\n" :: "r"(d), "l"(src));
}

__device__ __forceinline__ void mma_tf32(float c[4], uint32_t a0, uint32_t a1,
                                         uint32_t a2, uint32_t a3,
                                         uint32_t b0, uint32_t b1) {
    asm volatile(
        "mma.sync.aligned.m16n8k8.row.col.f32.tf32.tf32.f32 "
        "{%0,%1,%2,%3}, {%4,%5,%6,%7}, {%8,%9}, {%0,%1,%2,%3};"
        : "+f"(c[0]), "+f"(c[1]), "+f"(c[2]), "+f"(c[3])
        : "r"(a0), "r"(a1), "r"(a2), "r"(a3), "r"(b0), "r"(b1));
}

// ---------------------------------------------------------------------------
// Unified TF32 tensor-core GEMM, 64x32 tile/CTA, 128 threads (4 warps),
// KT=64 k-slabs, 2-stage cp.async, 4 CTAs/SM -> agg grid fully resident.
//   MODE 0: XW1       A=x, K=128, B=w1 (raw fp32 bits) -> g_Tt (tf32)
//           (also resets g_cnt tickets)
//   MODE 1: AGG1+HW2  A=a[b], K=2048, B=g_Tt  -> T2 -> g_T2t
//   MODE 3: AGG2+POOL A=a[b], K=2048, B=g_T2t -> poolpart; last CTA per batch
//           computes the FC head inline (deterministic fixed-order sums).
// ---------------------------------------------------------------------------
template <int MODE>
__global__ void __launch_bounds__(128, 4)
k_gemm(const float* __restrict__ Abase, const float* __restrict__ bias,
       const float* __restrict__ aux,
       const float* __restrict__ wf1, const float* __restrict__ bf1,
       const float* __restrict__ wf2, const float* __restrict__ bf2,
       float* __restrict__ out) {
    constexpr bool AGG = (MODE != 0);
    constexpr int LDA = AGG ? N_ : F_;
    constexpr int NKT = LDA / KT;          // 32 (agg) or 2 (xw1)

    extern __shared__ __align__(16) char smem[];
    float (*As)[TM][PA] = (float(*)[TM][PA])smem;
    uint32_t (*Ts)[KT][PT] = (uint32_t(*)[KT][PT])(smem + 2 * TM * PA * 4);
    float (*red)[C1] = (float(*)[C1])(smem + 2 * TM * PA * 4 + 2 * KT * PT * 4);

    const int tid = threadIdx.x;            // 128
    const int b = AGG ? blockIdx.y : 0;
    const int t0 = blockIdx.x * TM;

    if (MODE == 0 && blockIdx.x < B_ && tid == 0) g_cnt[blockIdx.x] = 0;

    const float* A = Abase + (AGG ? ((size_t)b * N_ + t0) * N_ : (size_t)t0 * LDA);
    const uint32_t* Bp = (MODE == 0) ? (const uint32_t*)aux
                       : ((MODE == 1 ? g_Tt : g_T2t) + (size_t)b * N_ * C1);

    const int wid = tid >> 5;               // 0..3 -> rows wid*16..+15
    const int lane = tid & 31;
    const int g = lane >> 2;                // 0..7
    const int q = lane & 3;                 // 0..3
    const int rm = wid * 16;

    float acc[4][4];
#pragma unroll
    for (int j = 0; j < 4; j++)
#pragma unroll
        for (int i = 0; i < 4; i++) acc[j][i] = 0.f;

    // stage loader: A slab 64x64 (8 cp16/thread), T slab 64x32 (4 cp16/thread)
    auto load_stage = [&](int s, int k0) {
#pragma unroll
        for (int i = 0; i < 8; i++) {
            const int idx = tid + 128 * i;
            const int r = idx >> 4, c4 = (idx & 15) * 4;
            cp16(&As[s][r][c4], A + (size_t)r * LDA + k0 + c4);
        }
#pragma unroll
        for (int i = 0; i < 4; i++) {
            const int idx = tid + 128 * i;
            const int r = idx >> 3, c4 = (idx & 7) * 4;
            cp16(&Ts[s][r][c4], Bp + (size_t)(k0 + r) * C1 + c4);
        }
        asm volatile("cp.async.commit_group;\n");
    };

    load_stage(0, 0);

    for (int kt = 0; kt < NKT; kt++) {
        const int cur = kt & 1;
        if (kt + 1 < NKT) {
            load_stage(cur ^ 1, (kt + 1) * KT);
            asm volatile("cp.async.wait_group 1;\n");
        } else {
            asm volatile("cp.async.wait_group 0;\n");
        }
        __syncthreads();

#pragma unroll
        for (int k8 = 0; k8 < KT / 8; k8++) {
            const int kk = k8 * 8;
            uint32_t A0 = __float_as_uint(As[cur][rm + g][kk + q]);
            uint32_t A1 = __float_as_uint(As[cur][rm + g + 8][kk + q]);
            uint32_t A2 = __float_as_uint(As[cur][rm + g][kk + q + 4]);
            uint32_t A3 = __float_as_uint(As[cur][rm + g + 8][kk + q + 4]);
#pragma unroll
            for (int j = 0; j < 4; j++) {
                uint32_t B0 = Ts[cur][kk + q][8 * j + g];
                uint32_t B1 = Ts[cur][kk + q + 4][8 * j + g];
                mma_tf32(acc[j], A0, A1, A2, A3, B0, B1);
            }
        }
        __syncthreads();
    }

    if (MODE == 0) {
#pragma unroll
        for (int j = 0; j < 4; j++) {
            const int col = 8 * j + 2 * q;
            const size_t r0 = ((size_t)t0 + rm + g) * C1 + col;
            const size_t r1 = r0 + 8 * C1;
            *(uint2*)&g_Tt[r0] = make_uint2(f2tf(acc[j][0]), f2tf(acc[j][1]));
            *(uint2*)&g_Tt[r1] = make_uint2(f2tf(acc[j][2]), f2tf(acc[j][3]));
        }
    } else if (MODE == 1) {
        // H tile = elu(acc + b1) -> smem (reuse As[0]); W2 -> smem (reuse Ts)
        float (*Hs)[PA] = As[0];
#pragma unroll
        for (int j = 0; j < 4; j++) {
            const int col = 8 * j + 2 * q;
            const float bc0 = bias[col], bc1 = bias[col + 1];
            *(float2*)&Hs[rm + g][col] =
                make_float2(elu_f(acc[j][0] + bc0), elu_f(acc[j][1] + bc1));
            *(float2*)&Hs[rm + g + 8][col] =
                make_float2(elu_f(acc[j][2] + bc0), elu_f(acc[j][3] + bc1));
        }
        float* Ws = (float*)Ts;
        for (int i = tid; i < C1 * C1; i += 128) Ws[i] = aux[i];
        __syncthreads();
        // T2 = H @ W2 (fp32): thread -> row r = tid>>1, 16 cols at ch
        const int r = tid >> 1;
        const int ch = (tid & 1) * 16;
        float t2[16];
#pragma unroll
        for (int c = 0; c < 16; c++) t2[c] = 0.f;
#pragma unroll
        for (int k = 0; k < C1; k++) {
            const float h = Hs[r][k];
#pragma unroll
            for (int c = 0; c < 16; c++) t2[c] += h * Ws[k * C1 + ch + c];
        }
        uint32_t* op = &g_T2t[((size_t)b * N_ + t0 + r) * C1 + ch];
#pragma unroll
        for (int c4 = 0; c4 < 4; c4++)
            *(uint4*)&op[c4 * 4] = make_uint4(f2tf(t2[c4 * 4]), f2tf(t2[c4 * 4 + 1]),
                                              f2tf(t2[c4 * 4 + 2]), f2tf(t2[c4 * 4 + 3]));
    } else {
        // pool: colsum of elu(acc + b2) -> per-tile partials
#pragma unroll
        for (int j = 0; j < 4; j++) {
            const int col = 8 * j + 2 * q;
            const float bc0 = bias[col], bc1 = bias[col + 1];
            float s0 = elu_f(acc[j][0] + bc0) + elu_f(acc[j][2] + bc0);
            float s1 = elu_f(acc[j][1] + bc1) + elu_f(acc[j][3] + bc1);
#pragma unroll
            for (int m = 4; m < 32; m <<= 1) {   // reduce over g (lanes q+4g)
                s0 += __shfl_xor_sync(0xffffffffu, s0, m);
                s1 += __shfl_xor_sync(0xffffffffu, s1, m);
            }
            if (g == 0) {
                red[wid][col] = s0;
                red[wid][col + 1] = s1;
            }
        }
        __syncthreads();
        if (tid < C1) {
            g_poolpart[((size_t)b * NTILES + blockIdx.x) * C1 + tid] =
                red[0][tid] + red[1][tid] + red[2][tid] + red[3][tid];
        }
        __threadfence();
        __syncthreads();

        // Last CTA of this batch computes the FC head (deterministic: atomics
        // only elect the CTA; all float sums are fixed-order).
        __shared__ int s_last;
        if (tid == 0) {
            int old = atomicAdd(&g_cnt[b], 1);
            s_last = (old == NTILES - 1);
        }
        __syncthreads();
        if (s_last) {
            __threadfence();
            float* ps = &red[0][0];   // 32 pooled values
            float* wp = &red[1][0];   // 4 warp partials
            if (tid < C1) {
                float s = 0.f;
#pragma unroll
                for (int t = 0; t < NTILES; t++)
                    s += g_poolpart[((size_t)b * NTILES + t) * C1 + tid];
                ps[tid] = s;
            }
            __syncthreads();
            float v = 0.f;
#pragma unroll
            for (int i = 0; i < 4; i++) {
                const int o = tid + 128 * i;
                float z = bf1[o];
#pragma unroll
                for (int k = 0; k < C1; k++)
                    z += ps[k] * wf1[k * 512 + o];
                v += fmaxf(z, 0.f) * wf2[o];
            }
#pragma unroll
            for (int m = 16; m > 0; m >>= 1) v += __shfl_xor_sync(0xffffffffu, v, m);
            if (lane == 0) wp[wid] = v;
            __syncthreads();
            if (tid == 0) {
                float s = wp[0] + wp[1] + wp[2] + wp[3];
                out[b] = 1.f / (1.f + __expf(-(s + bf2[0])));
            }
        }
    }
}

// ---------------------------------------------------------------------------
extern "C" void kernel_launch(void* const* d_in, const int* in_sizes, int n_in,
                              void* d_out, int out_size) {
    const float* x   = (const float*)d_in[0];
    const float* a   = (const float*)d_in[1];
    const float* w1  = (const float*)d_in[2];
    const float* b1  = (const float*)d_in[3];
    const float* w2  = (const float*)d_in[4];
    const float* b2  = (const float*)d_in[5];
    const float* wf1 = (const float*)d_in[6];
    const float* bf1 = (const float*)d_in[7];
    const float* wf2 = (const float*)d_in[8];
    const float* bf2 = (const float*)d_in[9];
    float* out = (float*)d_out;

    (void)in_sizes; (void)n_in; (void)out_size;

    cudaFuncSetAttribute(k_gemm<0>, cudaFuncAttributeMaxDynamicSharedMemorySize, SMEM_BYTES);
    cudaFuncSetAttribute(k_gemm<1>, cudaFuncAttributeMaxDynamicSharedMemorySize, SMEM_BYTES);
    cudaFuncSetAttribute(k_gemm<3>, cudaFuncAttributeMaxDynamicSharedMemorySize, SMEM_BYTES);

    dim3 gagg(NTILES, B_);   // 32 x 16 = 512 CTAs, fully resident @4 CTAs/SM

    k_gemm<0><<<(B_ * N_) / TM, 128, SMEM_BYTES>>>(
        x, nullptr, w1, nullptr, nullptr, nullptr, nullptr, nullptr);
    k_gemm<1><<<gagg, 128, SMEM_BYTES>>>(
        a, b1, w2, nullptr, nullptr, nullptr, nullptr, nullptr);
    k_gemm<3><<<gagg, 128, SMEM_BYTES>>>(
        a, b2, nullptr, wf1, bf1, wf2, bf2, out);   // agg2 + pool + fused head
}

// round 16
// speedup vs baseline: 1.0041x; 1.0041x over previous
#include <cuda_runtime.h>
#include <cstdint>

#define B_ 16
#define N_ 2048
#define F_ 128
#define C1 32
#define TM 64              // rows per CTA tile
#define KT 64              // k-slab: 256B contiguous per A row
#define PA 68              // As pitch: 68%32=4 -> A frags conflict-free
#define PT 40              // Ts pitch: conflict-free B frags
#define NTILES (N_ / TM)   // 32

#define SMEM_BYTES (2*TM*PA*4 + 2*KT*PT*4 + 4*C1*4)   // 55808 B -> 4 CTAs/SM

// Scratch (static device globals — no allocation allowed)
__device__ uint32_t g_Tt[B_ * N_ * C1];      // T1 = X@W1 as tf32 bits
__device__ uint32_t g_T2t[B_ * N_ * C1];     // T2 = elu(A@T1+b1)@W2 as tf32 bits
__device__ float    g_poolpart[B_ * NTILES * C1];
__device__ int      g_cnt[B_];               // agg2 completion tickets per batch

__device__ __forceinline__ float elu_f(float x) {
    return x > 0.f ? x : (__expf(x) - 1.f);
}

__device__ __forceinline__ uint32_t f2tf(float f) {
    uint32_t r;
    asm("cvt.rna.tf32.f32 %0, %1;" : "=r"(r) : "f"(f));
    return r;
}

__device__ __forceinline__ void cp16(void* dst, const void* src) {
    uint32_t d = (uint32_t)__cvta_generic_to_shared(dst);
    asm volatile("cp.async.cg.shared.global [%0], [%1], 16;\n" :: "r"(d), "l"(src));
}

__device__ __forceinline__ void mma_tf32(float c[4], uint32_t a0, uint32_t a1,
                                         uint32_t a2, uint32_t a3,
                                         uint32_t b0, uint32_t b1) {
    asm volatile(
        "mma.sync.aligned.m16n8k8.row.col.f32.tf32.tf32.f32 "
        "{%0,%1,%2,%3}, {%4,%5,%6,%7}, {%8,%9}, {%0,%1,%2,%3};"
        : "+f"(c[0]), "+f"(c[1]), "+f"(c[2]), "+f"(c[3])
        : "r"(a0), "r"(a1), "r"(a2), "r"(a3), "r"(b0), "r"(b1));
}

// ---------------------------------------------------------------------------
// Unified TF32 tensor-core GEMM, 64x32 tile/CTA, 128 threads (4 warps),
// KT=64 k-slabs, 2-stage cp.async, 4 CTAs/SM -> agg grid fully resident.
//   MODE 0: XW1       A=x, K=128, B=w1 (raw fp32 bits) -> g_Tt (tf32)
//           (also resets g_cnt tickets)
//   MODE 1: AGG1+HW2  A=a[b], K=2048, B=g_Tt  -> T2 -> g_T2t
//   MODE 3: AGG2+POOL A=a[b], K=2048, B=g_T2t -> poolpart; last CTA per batch
//           computes the FC head inline (deterministic fixed-order sums).
// ---------------------------------------------------------------------------
template <int MODE>
__global__ void __launch_bounds__(128, 4)
k_gemm(const float* __restrict__ Abase, const float* __restrict__ bias,
       const float* __restrict__ aux,
       const float* __restrict__ wf1, const float* __restrict__ bf1,
       const float* __restrict__ wf2, const float* __restrict__ bf2,
       float* __restrict__ out) {
    constexpr bool AGG = (MODE != 0);
    constexpr int LDA = AGG ? N_ : F_;
    constexpr int NKT = LDA / KT;          // 32 (agg) or 2 (xw1)

    extern __shared__ __align__(16) char smem[];
    float (*As)[TM][PA] = (float(*)[TM][PA])smem;
    uint32_t (*Ts)[KT][PT] = (uint32_t(*)[KT][PT])(smem + 2 * TM * PA * 4);
    float (*red)[C1] = (float(*)[C1])(smem + 2 * TM * PA * 4 + 2 * KT * PT * 4);

    const int tid = threadIdx.x;            // 128
    const int b = AGG ? blockIdx.y : 0;
    const int t0 = blockIdx.x * TM;

    if (MODE == 0 && blockIdx.x < B_ && tid == 0) g_cnt[blockIdx.x] = 0;

    const float* A = Abase + (AGG ? ((size_t)b * N_ + t0) * N_ : (size_t)t0 * LDA);
    const uint32_t* Bp = (MODE == 0) ? (const uint32_t*)aux
                       : ((MODE == 1 ? g_Tt : g_T2t) + (size_t)b * N_ * C1);

    const int wid = tid >> 5;               // 0..3 -> rows wid*16..+15
    const int lane = tid & 31;
    const int g = lane >> 2;                // 0..7
    const int q = lane & 3;                 // 0..3
    const int rm = wid * 16;

    float acc[4][4];
#pragma unroll
    for (int j = 0; j < 4; j++)
#pragma unroll
        for (int i = 0; i < 4; i++) acc[j][i] = 0.f;

    // stage loader: A slab 64x64 (8 cp16/thread), T slab 64x32 (4 cp16/thread)
    auto load_stage = [&](int s, int k0) {
#pragma unroll
        for (int i = 0; i < 8; i++) {
            const int idx = tid + 128 * i;
            const int r = idx >> 4, c4 = (idx & 15) * 4;
            cp16(&As[s][r][c4], A + (size_t)r * LDA + k0 + c4);
        }
#pragma unroll
        for (int i = 0; i < 4; i++) {
            const int idx = tid + 128 * i;
            const int r = idx >> 3, c4 = (idx & 7) * 4;
            cp16(&Ts[s][r][c4], Bp + (size_t)(k0 + r) * C1 + c4);
        }
        asm volatile("cp.async.commit_group;\n");
    };

    load_stage(0, 0);

    for (int kt = 0; kt < NKT; kt++) {
        const int cur = kt & 1;
        if (kt + 1 < NKT) {
            load_stage(cur ^ 1, (kt + 1) * KT);
            asm volatile("cp.async.wait_group 1;\n");
        } else {
            asm volatile("cp.async.wait_group 0;\n");
        }
        __syncthreads();

#pragma unroll
        for (int k8 = 0; k8 < KT / 8; k8++) {
            const int kk = k8 * 8;
            uint32_t A0 = __float_as_uint(As[cur][rm + g][kk + q]);
            uint32_t A1 = __float_as_uint(As[cur][rm + g + 8][kk + q]);
            uint32_t A2 = __float_as_uint(As[cur][rm + g][kk + q + 4]);
            uint32_t A3 = __float_as_uint(As[cur][rm + g + 8][kk + q + 4]);
#pragma unroll
            for (int j = 0; j < 4; j++) {
                uint32_t B0 = Ts[cur][kk + q][8 * j + g];
                uint32_t B1 = Ts[cur][kk + q + 4][8 * j + g];
                mma_tf32(acc[j], A0, A1, A2, A3, B0, B1);
            }
        }
        __syncthreads();
    }

    if (MODE == 0) {
#pragma unroll
        for (int j = 0; j < 4; j++) {
            const int col = 8 * j + 2 * q;
            const size_t r0 = ((size_t)t0 + rm + g) * C1 + col;
            const size_t r1 = r0 + 8 * C1;
            *(uint2*)&g_Tt[r0] = make_uint2(f2tf(acc[j][0]), f2tf(acc[j][1]));
            *(uint2*)&g_Tt[r1] = make_uint2(f2tf(acc[j][2]), f2tf(acc[j][3]));
        }
    } else if (MODE == 1) {
        // H tile = elu(acc + b1) -> smem (reuse As[0]); W2 -> smem (reuse Ts)
        float (*Hs)[PA] = As[0];
#pragma unroll
        for (int j = 0; j < 4; j++) {
            const int col = 8 * j + 2 * q;
            const float bc0 = bias[col], bc1 = bias[col + 1];
            *(float2*)&Hs[rm + g][col] =
                make_float2(elu_f(acc[j][0] + bc0), elu_f(acc[j][1] + bc1));
            *(float2*)&Hs[rm + g + 8][col] =
                make_float2(elu_f(acc[j][2] + bc0), elu_f(acc[j][3] + bc1));
        }
        float* Ws = (float*)Ts;
        for (int i = tid; i < C1 * C1; i += 128) Ws[i] = aux[i];
        __syncthreads();
        // T2 = H @ W2 (fp32): thread -> row r = tid>>1, 16 cols at ch
        const int r = tid >> 1;
        const int ch = (tid & 1) * 16;
        float t2[16];
#pragma unroll
        for (int c = 0; c < 16; c++) t2[c] = 0.f;
#pragma unroll
        for (int k = 0; k < C1; k++) {
            const float h = Hs[r][k];
#pragma unroll
            for (int c = 0; c < 16; c++) t2[c] += h * Ws[k * C1 + ch + c];
        }
        uint32_t* op = &g_T2t[((size_t)b * N_ + t0 + r) * C1 + ch];
#pragma unroll
        for (int c4 = 0; c4 < 4; c4++)
            *(uint4*)&op[c4 * 4] = make_uint4(f2tf(t2[c4 * 4]), f2tf(t2[c4 * 4 + 1]),
                                              f2tf(t2[c4 * 4 + 2]), f2tf(t2[c4 * 4 + 3]));
    } else {
        // pool: colsum of elu(acc + b2) -> per-tile partials
#pragma unroll
        for (int j = 0; j < 4; j++) {
            const int col = 8 * j + 2 * q;
            const float bc0 = bias[col], bc1 = bias[col + 1];
            float s0 = elu_f(acc[j][0] + bc0) + elu_f(acc[j][2] + bc0);
            float s1 = elu_f(acc[j][1] + bc1) + elu_f(acc[j][3] + bc1);
#pragma unroll
            for (int m = 4; m < 32; m <<= 1) {   // reduce over g (lanes q+4g)
                s0 += __shfl_xor_sync(0xffffffffu, s0, m);
                s1 += __shfl_xor_sync(0xffffffffu, s1, m);
            }
            if (g == 0) {
                red[wid][col] = s0;
                red[wid][col + 1] = s1;
            }
        }
        __syncthreads();
        if (tid < C1) {
            g_poolpart[((size_t)b * NTILES + blockIdx.x) * C1 + tid] =
                red[0][tid] + red[1][tid] + red[2][tid] + red[3][tid];
        }
        __threadfence();
        __syncthreads();

        // Last CTA of this batch computes the FC head (deterministic: atomics
        // only elect the CTA; all float sums are fixed-order).
        __shared__ int s_last;
        if (tid == 0) {
            int old = atomicAdd(&g_cnt[b], 1);
            s_last = (old == NTILES - 1);
        }
        __syncthreads();
        if (s_last) {
            __threadfence();
            float* ps = &red[0][0];   // 32 pooled values
            float* wp = &red[1][0];   // 4 warp partials
            if (tid < C1) {
                float s = 0.f;
#pragma unroll
                for (int t = 0; t < NTILES; t++)
                    s += g_poolpart[((size_t)b * NTILES + t) * C1 + tid];
                ps[tid] = s;
            }
            __syncthreads();
            float v = 0.f;
#pragma unroll
            for (int i = 0; i < 4; i++) {
                const int o = tid + 128 * i;
                float z = bf1[o];
#pragma unroll
                for (int k = 0; k < C1; k++)
                    z += ps[k] * wf1[k * 512 + o];
                v += fmaxf(z, 0.f) * wf2[o];
            }
#pragma unroll
            for (int m = 16; m > 0; m >>= 1) v += __shfl_xor_sync(0xffffffffu, v, m);
            if (lane == 0) wp[wid] = v;
            __syncthreads();
            if (tid == 0) {
                float s = wp[0] + wp[1] + wp[2] + wp[3];
                out[b] = 1.f / (1.f + __expf(-(s + bf2[0])));
            }
        }
    }
}

// ---------------------------------------------------------------------------
extern "C" void kernel_launch(void* const* d_in, const int* in_sizes, int n_in,
                              void* d_out, int out_size) {
    const float* x   = (const float*)d_in[0];
    const float* a   = (const float*)d_in[1];
    const float* w1  = (const float*)d_in[2];
    const float* b1  = (const float*)d_in[3];
    const float* w2  = (const float*)d_in[4];
    const float* b2  = (const float*)d_in[5];
    const float* wf1 = (const float*)d_in[6];
    const float* bf1 = (const float*)d_in[7];
    const float* wf2 = (const float*)d_in[8];
    const float* bf2 = (const float*)d_in[9];
    float* out = (float*)d_out;

    (void)in_sizes; (void)n_in; (void)out_size;

    cudaFuncSetAttribute(k_gemm<0>, cudaFuncAttributeMaxDynamicSharedMemorySize, SMEM_BYTES);
    cudaFuncSetAttribute(k_gemm<1>, cudaFuncAttributeMaxDynamicSharedMemorySize, SMEM_BYTES);
    cudaFuncSetAttribute(k_gemm<3>, cudaFuncAttributeMaxDynamicSharedMemorySize, SMEM_BYTES);

    dim3 gagg(NTILES, B_);   // 32 x 16 = 512 CTAs, fully resident @4 CTAs/SM

    k_gemm<0><<<(B_ * N_) / TM, 128, SMEM_BYTES>>>(
        x, nullptr, w1, nullptr, nullptr, nullptr, nullptr, nullptr);
    k_gemm<1><<<gagg, 128, SMEM_BYTES>>>(
        a, b1, w2, nullptr, nullptr, nullptr, nullptr, nullptr);
    k_gemm<3><<<gagg, 128, SMEM_BYTES>>>(
        a, b2, nullptr, wf1, bf1, wf2, bf2, out);   // agg2 + pool + fused head
}